// round 3
// baseline (speedup 1.0000x reference)
#include <cuda_runtime.h>

typedef unsigned long long u64;

#define S_LEN   2048
#define HID     4096
#define QKV_OUT 6144
#define NH      32
#define NKV     8
#define HD      128

// Scratch (device globals; .bss zero-initialized at load). qkv has 64 padding
// rows so the last attention K-tile (rows up to 2063) never reads OOB; padded
// rows are never written, stay zero, and are causally masked anyway.
__device__ float g_qkv[(S_LEN + 64) * QKV_OUT];
__device__ float g_attn[S_LEN * NH * HD];

// ---------------- packed f32x2 helpers ----------------
__device__ __forceinline__ u64 ffma2(u64 a, u64 b, u64 c) {
    u64 d;
    asm("fma.rn.f32x2 %0, %1, %2, %3;" : "=l"(d) : "l"(a), "l"(b), "l"(c));
    return d;
}
__device__ __forceinline__ u64 fmul2(u64 a, u64 b) {
    u64 d;
    asm("mul.rn.f32x2 %0, %1, %2;" : "=l"(d) : "l"(a), "l"(b));
    return d;
}
__device__ __forceinline__ u64 splat2(float x) {
    u64 d;
    unsigned int u = __float_as_uint(x);
    asm("mov.b64 %0, {%1, %1};" : "=l"(d) : "r"(u));
    return d;
}
__device__ __forceinline__ float hadd2(u64 a) {
    unsigned int lo, hi;
    asm("mov.b64 {%0, %1}, %2;" : "=r"(lo), "=r"(hi) : "l"(a));
    return __uint_as_float(lo) + __uint_as_float(hi);
}

// ---------------- GEMM: C[M,N] = A[M,K] * B[N,K]^T (both K-major) ----------------
// 128x128x32 tile, 256 threads, 8x8 per-thread micro-tile in packed f32x2.
// Software pipeline: global loads for tile k+1 staged in regs during compute of k.
#define TBM 128
#define TBN 128
#define TBK 32
#define PADM 132   // 132*4 = 528 B rows: 16B-aligned, conflict-staggered

__global__ __launch_bounds__(256)   // no occupancy cap -> no forced spills
void gemm_tn(const float* __restrict__ A, const float* __restrict__ B,
             float* __restrict__ C, int M, int N, int K) {
    __shared__ float As[TBK * PADM];
    __shared__ float Bs[TBK * PADM];

    const int tid = threadIdx.x;
    const int m0 = blockIdx.y * TBM;
    const int n0 = blockIdx.x * TBN;
    const int tm = tid >> 4;      // 0..15 -> rows tm*8..tm*8+7
    const int tn = tid & 15;      // 0..15 -> cols tn*8..tn*8+7

    // loader mapping: thread owns row r; even threads k-slots 0..3, odd 4..7
    const int r  = tid >> 1;            // 0..127
    const int c4 = (tid & 1) * 4;       // base float4 slot (0 or 4)
    const float* ap = A + (size_t)(m0 + r) * K + c4 * 4;
    const float* bp = B + (size_t)(n0 + r) * K + c4 * 4;

    u64 acc[8][4];
#pragma unroll
    for (int i = 0; i < 8; ++i)
#pragma unroll
        for (int j = 0; j < 4; ++j) acc[i][j] = 0ull;

    // prefetch tile 0 into registers
    float4 pa[4], pb[4];
#pragma unroll
    for (int it = 0; it < 4; ++it) {
        pa[it] = *(const float4*)(ap + it * 4);
        pb[it] = *(const float4*)(bp + it * 4);
    }

    const int ktiles = K / TBK;
    for (int kt = 0; kt < ktiles; ++kt) {
        __syncthreads();   // previous tile fully consumed
#pragma unroll
        for (int it = 0; it < 4; ++it) {
            int slot = c4 + it;                 // float4 slot 0..7 within k-slab
            As[(slot * 4 + 0) * PADM + r] = pa[it].x;
            As[(slot * 4 + 1) * PADM + r] = pa[it].y;
            As[(slot * 4 + 2) * PADM + r] = pa[it].z;
            As[(slot * 4 + 3) * PADM + r] = pa[it].w;
            Bs[(slot * 4 + 0) * PADM + r] = pb[it].x;
            Bs[(slot * 4 + 1) * PADM + r] = pb[it].y;
            Bs[(slot * 4 + 2) * PADM + r] = pb[it].z;
            Bs[(slot * 4 + 3) * PADM + r] = pb[it].w;
        }
        __syncthreads();

        // stage next tile's global loads behind this tile's compute
        if (kt + 1 < ktiles) {
            const float* apn = ap + (size_t)(kt + 1) * TBK;
            const float* bpn = bp + (size_t)(kt + 1) * TBK;
#pragma unroll
            for (int it = 0; it < 4; ++it) {
                pa[it] = *(const float4*)(apn + it * 4);
                pb[it] = *(const float4*)(bpn + it * 4);
            }
        }

#pragma unroll 8
        for (int kk = 0; kk < TBK; ++kk) {
            float4 a0 = *(const float4*)&As[kk * PADM + tm * 8];
            float4 a1 = *(const float4*)&As[kk * PADM + tm * 8 + 4];
            const u64* bp8 = (const u64*)&Bs[kk * PADM + tn * 8];
            u64 b0 = bp8[0], b1 = bp8[1], b2 = bp8[2], b3 = bp8[3];
            float av[8] = {a0.x, a0.y, a0.z, a0.w, a1.x, a1.y, a1.z, a1.w};
#pragma unroll
            for (int i = 0; i < 8; ++i) {
                u64 asx = splat2(av[i]);
                acc[i][0] = ffma2(asx, b0, acc[i][0]);
                acc[i][1] = ffma2(asx, b1, acc[i][1]);
                acc[i][2] = ffma2(asx, b2, acc[i][2]);
                acc[i][3] = ffma2(asx, b3, acc[i][3]);
            }
        }
    }

#pragma unroll
    for (int i = 0; i < 8; ++i) {
        float* crow = C + (size_t)(m0 + tm * 8 + i) * N + n0 + tn * 8;
        ulonglong2 v0; v0.x = acc[i][0]; v0.y = acc[i][1];
        ulonglong2 v1; v1.x = acc[i][2]; v1.y = acc[i][3];
        *(ulonglong2*)(crow)     = v0;
        *(ulonglong2*)(crow + 4) = v1;
    }
}

// QKV projection: writes into g_qkv (device global referenced directly)
__global__ __launch_bounds__(256)
void gemm_qkv(const float* __restrict__ A, const float* __restrict__ B) {
    // thin wrappers would duplicate 200 lines; instead call the body via
    // pointer math on the global. (Kernel bodies can't share easily without
    // templates; use a trampoline.)
    // -- implemented below as separate launches of gemm_tn with global addresses
}

// ---------------- RoPE (in-place on Q and K slices of qkv) ----------------
__global__ void rope_kernel() {
    int idx = blockIdx.x * blockDim.x + threadIdx.x;
    const int total = S_LEN * (NH + NKV) * 64;
    if (idx >= total) return;
    int i = idx & 63;
    int t = idx >> 6;
    int head = t % (NH + NKV);
    int s = t / (NH + NKV);
    int off = (head < NH) ? head * HD : HID + (head - NH) * HD;
    float* p = g_qkv + (size_t)s * QKV_OUT + off;
    float x1 = p[i];
    float x2 = p[i + 64];
    // double-precision angle/trig: immune to fast-math range reduction at ang~2047
    double freq = exp(-(double)i * (9.210340371976184 / 64.0));  // ln(10000)/64
    double ang = (double)s * freq;
    float c  = (float)cos(ang);
    float sn = (float)sin(ang);
    p[i]      = x1 * c - x2 * sn;
    p[i + 64] = x1 * sn + x2 * c;
}

// ---------------- Flash attention (fp32, causal, GQA) ----------------
// Grid: (16 q-tiles, 32 heads), heavy q-tiles launched FIRST (qt descending)
// for wave load balance. 256 threads; 4-thread group owns 2 q-rows x 32 dims.
#define KT 48

__global__ __launch_bounds__(256, 1)
void attn_kernel() {
    __shared__ float Ks[KT * HD];   // 24KB
    __shared__ float Vs[KT * HD];   // 24KB (48KB static)

    const int qt  = (gridDim.x - 1) - blockIdx.x;   // descending work order
    const int h   = blockIdx.y;
    const int kh  = h >> 2;
    const int tid = threadIdx.x;
    const int grp = tid >> 2;   // 0..63
    const int g   = tid & 3;    // dim slice g*32 .. g*32+31

    const float* qkv = g_qkv;
    float* out = g_attn;

    const int q0 = qt * 128 + 2 * grp;
    const int q1 = q0 + 1;

    // load Q (pre-scaled by 1/sqrt(128)) into packed regs
    u64 Qr0[16], Qr1[16];
    {
        const u64 sc2 = splat2(0.08838834764831845f);
        const u64* qp0 = (const u64*)(qkv + (size_t)q0 * QKV_OUT + h * HD + g * 32);
        const u64* qp1 = (const u64*)(qkv + (size_t)q1 * QKV_OUT + h * HD + g * 32);
#pragma unroll
        for (int i2 = 0; i2 < 16; ++i2) {
            Qr0[i2] = fmul2(qp0[i2], sc2);
            Qr1[i2] = fmul2(qp1[i2], sc2);
        }
    }

    u64 O0[16], O1[16];
#pragma unroll
    for (int i2 = 0; i2 < 16; ++i2) { O0[i2] = 0ull; O1[i2] = 0ull; }
    float rm0 = -1e30f, rm1 = -1e30f, l0 = 0.0f, l1 = 0.0f;

    const int qmax = qt * 128 + 127;
    const int nkt  = qmax / KT + 1;

    for (int kt = 0; kt < nkt; ++kt) {
        const int ktbase = kt * KT;
        __syncthreads();  // previous tile fully consumed
        // cooperative load of K and V tiles (48x128 each, float4-coalesced)
#pragma unroll
        for (int it = 0; it < 6; ++it) {
            int f4  = tid + it * 256;     // 0..1535
            int row = f4 >> 5;            // 0..47
            int cc  = f4 & 31;            // 0..31
            size_t base = (size_t)(ktbase + row) * QKV_OUT;
            ((float4*)Ks)[f4] = *((const float4*)(qkv + base + HID + kh * HD) + cc);
            ((float4*)Vs)[f4] = *((const float4*)(qkv + base + HID + NKV * HD + kh * HD) + cc);
        }
        __syncthreads();

        const bool diag = (ktbase + KT - 1 > qt * 128);

#pragma unroll 1
        for (int c = 0; c < KT / 16; ++c) {
            const int c16 = c * 16;
            float p0[16], p1[16];
            float tmax0 = -1e30f, tmax1 = -1e30f;

            // scores for this 16-column chunk
#pragma unroll
            for (int jj = 0; jj < 16; ++jj) {
                const int j = c16 + jj;
                const u64* kp = (const u64*)(Ks + j * HD + g * 32);
                u64 a0 = 0ull, a1 = 0ull;
#pragma unroll
                for (int i2 = 0; i2 < 16; ++i2) {
                    u64 kv = kp[i2];
                    a0 = ffma2(Qr0[i2], kv, a0);
                    a1 = ffma2(Qr1[i2], kv, a1);
                }
                float s0 = hadd2(a0);
                float s1 = hadd2(a1);
                s0 += __shfl_xor_sync(0xffffffffu, s0, 1);
                s0 += __shfl_xor_sync(0xffffffffu, s0, 2);
                s1 += __shfl_xor_sync(0xffffffffu, s1, 1);
                s1 += __shfl_xor_sync(0xffffffffu, s1, 2);
                if (diag) {
                    int jg = ktbase + j;
                    if (jg > q0) s0 = -1e30f;  // overwrite also kills padded-row garbage
                    if (jg > q1) s1 = -1e30f;
                }
                p0[jj] = s0; p1[jj] = s1;
                tmax0 = fmaxf(tmax0, s0);
                tmax1 = fmaxf(tmax1, s1);
            }

            // online softmax update
            float mn0 = fmaxf(rm0, tmax0);
            float mn1 = fmaxf(rm1, tmax1);
            float e0 = __expf(rm0 - mn0);
            float e1 = __expf(rm1 - mn1);
            rm0 = mn0; rm1 = mn1;
            float sum0 = 0.0f, sum1 = 0.0f;
#pragma unroll
            for (int jj = 0; jj < 16; ++jj) {
                p0[jj] = __expf(p0[jj] - mn0); sum0 += p0[jj];
                p1[jj] = __expf(p1[jj] - mn1); sum1 += p1[jj];
            }
            l0 = l0 * e0 + sum0;
            l1 = l1 * e1 + sum1;
            {
                u64 e0p = splat2(e0), e1p = splat2(e1);
#pragma unroll
                for (int i2 = 0; i2 < 16; ++i2) {
                    O0[i2] = fmul2(O0[i2], e0p);
                    O1[i2] = fmul2(O1[i2], e1p);
                }
            }

            // O += P * V
#pragma unroll
            for (int jj = 0; jj < 16; ++jj) {
                const int j = c16 + jj;
                const u64* vp = (const u64*)(Vs + j * HD + g * 32);
                u64 pp0 = splat2(p0[jj]);
                u64 pp1 = splat2(p1[jj]);
#pragma unroll
                for (int i2 = 0; i2 < 16; ++i2) {
                    u64 vv = vp[i2];
                    O0[i2] = ffma2(pp0, vv, O0[i2]);
                    O1[i2] = ffma2(pp1, vv, O1[i2]);
                }
            }
        }
    }

    // epilogue: O / l -> out[q, h*128 + dims]
    u64 iv0 = splat2(1.0f / l0);
    u64 iv1 = splat2(1.0f / l1);
    u64* op0 = (u64*)(out + (size_t)q0 * (NH * HD) + h * HD + g * 32);
    u64* op1 = (u64*)(out + (size_t)q1 * (NH * HD) + h * HD + g * 32);
#pragma unroll
    for (int i2 = 0; i2 < 16; ++i2) {
        op0[i2] = fmul2(O0[i2], iv0);
        op1[i2] = fmul2(O1[i2], iv1);
    }
}

// trampolines so GEMM kernels address the device globals directly
__global__ __launch_bounds__(256)
void gemm_qkv_launcher(const float* __restrict__ A, const float* __restrict__ B);
__global__ __launch_bounds__(256)
void gemm_out_launcher(const float* __restrict__ B, float* __restrict__ C);

// ---------------- launch ----------------
extern "C" void kernel_launch(void* const* d_in, const int* in_sizes, int n_in,
                              void* d_out, int out_size) {
    const float* hs   = (const float*)d_in[0];   // [2048, 4096]
    const float* wqkv = (const float*)d_in[1];   // [6144, 4096]
    const float* wo   = (const float*)d_in[2];   // [4096, 4096]
    float* out = (float*)d_out;                  // [2048, 4096]

    // device-global scratch addresses (host-side query; NOT an allocation).
    // cudaGetSymbolAddress is a metadata lookup and is capture-safe, but we
    // call it outside any kernel-ordering concern anyway.
    void* qkv_ptr = 0;
    void* attn_ptr = 0;
    cudaGetSymbolAddress(&qkv_ptr, g_qkv);
    cudaGetSymbolAddress(&attn_ptr, g_attn);
    float* qkv  = (float*)qkv_ptr;
    float* attn = (float*)attn_ptr;

    // 1) QKV projection: [2048,6144] = hs @ wqkv^T
    {
        dim3 grid(QKV_OUT / TBN, S_LEN / TBM);
        gemm_tn<<<grid, 256>>>(hs, wqkv, qkv, S_LEN, QKV_OUT, HID);
    }
    // 2) RoPE on Q and K slices
    {
        int total = S_LEN * (NH + NKV) * 64;
        rope_kernel<<<(total + 255) / 256, 256>>>();
    }
    // 3) causal GQA flash attention -> g_attn [2048, 4096]
    {
        dim3 grid(S_LEN / 128, NH);
        attn_kernel<<<grid, 256>>>();
    }
    // 4) output projection: out = attn @ wo^T
    {
        dim3 grid(HID / TBN, S_LEN / TBM);
        gemm_tn<<<grid, 256>>>(attn, wo, out, S_LEN, HID, HID);
    }
}

// satisfy declarations (unused trampolines kept out of launch path)
__global__ __launch_bounds__(256)
void gemm_qkv_launcher(const float* __restrict__ A, const float* __restrict__ B) {}
__global__ __launch_bounds__(256)
void gemm_out_launcher(const float* __restrict__ B, float* __restrict__ C) {}

// round 7
// speedup vs baseline: 1.4309x; 1.4309x over previous
#include <cuda_runtime.h>
#include <cuda_bf16.h>
#include <cstdint>

typedef unsigned long long u64;

#define S_LEN   2048
#define HID     4096
#define QKV_OUT 6144
#define NH      32
#define NKV     8
#define HD      128

// ---------------- device-global scratch (.bss, zero at load) ----------------
__device__ float g_qkv[(S_LEN + 64) * QKV_OUT];   // padded rows stay zero
__device__ float g_attn[S_LEN * NH * HD];

__device__ __nv_bfloat16 g_hs_hi[S_LEN * HID],     g_hs_lo[S_LEN * HID];
__device__ __nv_bfloat16 g_wqkv_hi[QKV_OUT * HID], g_wqkv_lo[QKV_OUT * HID];
__device__ __nv_bfloat16 g_wo_hi[HID * HID],       g_wo_lo[HID * HID];
__device__ __nv_bfloat16 g_ao_hi[S_LEN * HID],     g_ao_lo[S_LEN * HID];

// ---------------- helpers ----------------
__device__ __forceinline__ uint32_t smem_to_u32(const void* p) {
    uint32_t a;
    asm("{ .reg .u64 t; cvta.to.shared.u64 t, %1; cvt.u32.u64 %0, t; }" : "=r"(a) : "l"(p));
    return a;
}
#define SWZ128(o) ((o) ^ (((o) >> 3) & 0x70))

__device__ __forceinline__ void ldm_x4(uint32_t* r, uint32_t addr) {
    asm volatile("ldmatrix.sync.aligned.m8n8.x4.shared.b16 {%0,%1,%2,%3}, [%4];"
        : "=r"(r[0]), "=r"(r[1]), "=r"(r[2]), "=r"(r[3]) : "r"(addr));
}
__device__ __forceinline__ void mma16816(float* c, const uint32_t* a,
                                         uint32_t b0, uint32_t b1) {
    asm volatile("mma.sync.aligned.m16n8k16.row.col.f32.bf16.bf16.f32 "
        "{%0,%1,%2,%3}, {%4,%5,%6,%7}, {%8,%9}, {%0,%1,%2,%3};"
        : "+f"(c[0]), "+f"(c[1]), "+f"(c[2]), "+f"(c[3])
        : "r"(a[0]), "r"(a[1]), "r"(a[2]), "r"(a[3]), "r"(b0), "r"(b1));
}
__device__ __forceinline__ void cp16(uint32_t saddr, const void* gaddr) {
    asm volatile("cp.async.cg.shared.global [%0], [%1], 16;"
                 :: "r"(saddr), "l"(gaddr));
}
#define CP_COMMIT() asm volatile("cp.async.commit_group;" ::: "memory")
#define CP_WAIT(n)  asm volatile("cp.async.wait_group %0;" :: "n"(n) : "memory")

// ---------------- fp32 -> bf16 hi/lo split ----------------
__global__ void split_kernel(const float* __restrict__ src,
                             __nv_bfloat16* __restrict__ hi,
                             __nv_bfloat16* __restrict__ lo, int n) {
    int i = blockIdx.x * blockDim.x + threadIdx.x;
    if (i >= n) return;
    float x = src[i];
    __nv_bfloat16 h = __float2bfloat16_rn(x);
    float r = x - __bfloat162float(h);
    hi[i] = h;
    lo[i] = __float2bfloat16_rn(r);
}

// ---------------- 3xBF16 HMMA GEMM: C[M,N] = A[M,K] * B[N,K]^T ----------------
// Tile 128x128, BK=64 (128B rows, SW128). 8 warps: 2(m) x 4(n), warp tile 64x32.
// cp.async double-buffered chunks; per k16-step: 12 ldmatrix.x4 + 48 mma.
#define CHUNK_BYTES 65536                 // 4 tiles x 16KB (Ah, Al, Bh, Bl)
#define G_SMEM_BYTES (2 * CHUNK_BYTES)    // double buffer

__global__ __launch_bounds__(256)
void gemm3_hmma(const __nv_bfloat16* __restrict__ Ahi, const __nv_bfloat16* __restrict__ Alo,
                const __nv_bfloat16* __restrict__ Bhi, const __nv_bfloat16* __restrict__ Blo,
                float* __restrict__ C, int M, int N, int K) {
    extern __shared__ char smem[];
    const uint32_t sb = smem_to_u32(smem);

    const int tid  = threadIdx.x;
    const int wid  = tid >> 5;
    const int lane = tid & 31;
    const int wm   = wid & 1;        // m offset wm*64
    const int wn   = wid >> 1;       // n offset wn*32
    const int m0 = blockIdx.y * 128;
    const int n0 = blockIdx.x * 128;

    float acc[4][4][4];
#pragma unroll
    for (int mi = 0; mi < 4; ++mi)
#pragma unroll
        for (int ni = 0; ni < 4; ++ni)
#pragma unroll
            for (int r = 0; r < 4; ++r) acc[mi][ni][r] = 0.0f;

    const uint32_t lrow  = lane & 15;
    const uint32_t lhalf = (lane >> 4) * 16;

    // issue one chunk's loads (4 tiles x 16KB) into buffer buf
    auto issue_chunk = [&](int c, int buf) {
        const int k0 = c << 6;
        const uint32_t base = sb + buf * CHUNK_BYTES;
        const __nv_bfloat16* srcs[4] = {Ahi, Alo, Bhi, Blo};
#pragma unroll
        for (int arr = 0; arr < 4; ++arr) {
            const __nv_bfloat16* s = srcs[arr];
            const int rb = (arr < 2) ? m0 : n0;
            const uint32_t dst = base + arr * 16384;
#pragma unroll
            for (int it = 0; it < 4; ++it) {
                int u = tid + it * 256;          // 16B-unit index 0..1023
                int row = u >> 3, c16 = u & 7;
                const void* g = (const void*)(s + (size_t)(rb + row) * K + k0 + c16 * 8);
                cp16(dst + SWZ128((uint32_t)(row * 128 + c16 * 16)), g);
            }
        }
        CP_COMMIT();
    };

    const int nchunks = K >> 6;
    issue_chunk(0, 0);

    for (int c = 0; c < nchunks; ++c) {
        const int cur = c & 1;
        if (c + 1 < nchunks) {
            issue_chunk(c + 1, cur ^ 1);   // that buffer was drained before iter c began
            CP_WAIT(1);                    // chunk c resident (newest may stay in flight)
        } else {
            CP_WAIT(0);
        }
        __syncthreads();

        const uint32_t sAh = sb + cur * CHUNK_BYTES;
        const uint32_t sAl = sAh + 16384;
        const uint32_t sBh = sAh + 32768;
        const uint32_t sBl = sAh + 49152;

#pragma unroll
        for (int ks = 0; ks < 4; ++ks) {
            const uint32_t kb = ks * 32 + lhalf;
            uint32_t ah[4][4], al[4][4];
#pragma unroll
            for (int mi = 0; mi < 4; ++mi) {
                uint32_t row = wm * 64 + mi * 16 + lrow;
                uint32_t off = SWZ128(row * 128 + kb);
                ldm_x4(ah[mi], sAh + off);
                ldm_x4(al[mi], sAl + off);
            }
            uint32_t bh[2][4], bl[2][4];
#pragma unroll
            for (int np = 0; np < 2; ++np) {
                uint32_t row = wn * 32 + np * 16 + lrow;
                uint32_t off = SWZ128(row * 128 + kb);
                ldm_x4(bh[np], sBh + off);
                ldm_x4(bl[np], sBl + off);
            }
#pragma unroll
            for (int mi = 0; mi < 4; ++mi)
#pragma unroll
                for (int ni = 0; ni < 4; ++ni) {
                    const int pr = ni >> 1, s2 = ni & 1;
                    mma16816(acc[mi][ni], ah[mi], bh[pr][s2], bh[pr][s2 + 2]);
                    mma16816(acc[mi][ni], ah[mi], bl[pr][s2], bl[pr][s2 + 2]);
                    mma16816(acc[mi][ni], al[mi], bh[pr][s2], bh[pr][s2 + 2]);
                }
        }
        __syncthreads();   // all warps done reading buffer `cur` before refill
    }

    // ---- epilogue: c0,c1 -> (row lane>>2, col (lane&3)*2); c2,c3 -> row+8 ----
#pragma unroll
    for (int mi = 0; mi < 4; ++mi)
#pragma unroll
        for (int ni = 0; ni < 4; ++ni) {
            int row = m0 + wm * 64 + mi * 16 + (lane >> 2);
            int col = n0 + wn * 32 + ni * 8 + (lane & 3) * 2;
            float2 v0 = make_float2(acc[mi][ni][0], acc[mi][ni][1]);
            float2 v1 = make_float2(acc[mi][ni][2], acc[mi][ni][3]);
            *(float2*)(C + (size_t)row * N + col)       = v0;
            *(float2*)(C + (size_t)(row + 8) * N + col) = v1;
        }
}

// ---------------- packed f32x2 helpers (attention) ----------------
__device__ __forceinline__ u64 ffma2(u64 a, u64 b, u64 c) {
    u64 d; asm("fma.rn.f32x2 %0, %1, %2, %3;" : "=l"(d) : "l"(a), "l"(b), "l"(c)); return d;
}
__device__ __forceinline__ u64 fmul2(u64 a, u64 b) {
    u64 d; asm("mul.rn.f32x2 %0, %1, %2;" : "=l"(d) : "l"(a), "l"(b)); return d;
}
__device__ __forceinline__ u64 splat2(float x) {
    u64 d; unsigned int u = __float_as_uint(x);
    asm("mov.b64 %0, {%1, %1};" : "=l"(d) : "r"(u)); return d;
}
__device__ __forceinline__ float hadd2(u64 a) {
    unsigned int lo, hi;
    asm("mov.b64 {%0, %1}, %2;" : "=r"(lo), "=r"(hi) : "l"(a));
    return __uint_as_float(lo) + __uint_as_float(hi);
}

// ---------------- RoPE (in-place on Q and K slices of g_qkv) ----------------
__global__ void rope_kernel() {
    int idx = blockIdx.x * blockDim.x + threadIdx.x;
    const int total = S_LEN * (NH + NKV) * 64;
    if (idx >= total) return;
    int i = idx & 63;
    int t = idx >> 6;
    int head = t % (NH + NKV);
    int s = t / (NH + NKV);
    int off = (head < NH) ? head * HD : HID + (head - NH) * HD;
    float* p = g_qkv + (size_t)s * QKV_OUT + off;
    float x1 = p[i];
    float x2 = p[i + 64];
    double freq = exp(-(double)i * (9.210340371976184 / 64.0));  // ln(10000)/64
    double ang = (double)s * freq;
    float c  = (float)cos(ang);
    float sn = (float)sin(ang);
    p[i]      = x1 * c - x2 * sn;
    p[i + 64] = x1 * sn + x2 * c;
}

// ---------------- Flash attention (fp32, causal, GQA) ----------------
#define KT 48

__global__ __launch_bounds__(256, 1)
void attn_kernel() {
    __shared__ float Ks[KT * HD];
    __shared__ float Vs[KT * HD];

    const int qt  = (gridDim.x - 1) - blockIdx.x;   // heavy tiles first
    const int h   = blockIdx.y;
    const int kh  = h >> 2;
    const int tid = threadIdx.x;
    const int grp = tid >> 2;
    const int g   = tid & 3;

    const float* qkv = g_qkv;
    float* out = g_attn;

    const int q0 = qt * 128 + 2 * grp;
    const int q1 = q0 + 1;

    u64 Qr0[16], Qr1[16];
    {
        const u64 sc2 = splat2(0.08838834764831845f);
        const u64* qp0 = (const u64*)(qkv + (size_t)q0 * QKV_OUT + h * HD + g * 32);
        const u64* qp1 = (const u64*)(qkv + (size_t)q1 * QKV_OUT + h * HD + g * 32);
#pragma unroll
        for (int i2 = 0; i2 < 16; ++i2) {
            Qr0[i2] = fmul2(qp0[i2], sc2);
            Qr1[i2] = fmul2(qp1[i2], sc2);
        }
    }

    u64 O0[16], O1[16];
#pragma unroll
    for (int i2 = 0; i2 < 16; ++i2) { O0[i2] = 0ull; O1[i2] = 0ull; }
    float rm0 = -1e30f, rm1 = -1e30f, l0 = 0.0f, l1 = 0.0f;

    const int qmax = qt * 128 + 127;
    const int nkt  = qmax / KT + 1;

    for (int kt = 0; kt < nkt; ++kt) {
        const int ktbase = kt * KT;
        __syncthreads();
#pragma unroll
        for (int it = 0; it < 6; ++it) {
            int f4  = tid + it * 256;
            int row = f4 >> 5;
            int cc  = f4 & 31;
            size_t base = (size_t)(ktbase + row) * QKV_OUT;
            ((float4*)Ks)[f4] = *((const float4*)(qkv + base + HID + kh * HD) + cc);
            ((float4*)Vs)[f4] = *((const float4*)(qkv + base + HID + NKV * HD + kh * HD) + cc);
        }
        __syncthreads();

        const bool diag = (ktbase + KT - 1 > qt * 128);

#pragma unroll 1
        for (int c = 0; c < KT / 16; ++c) {
            const int c16 = c * 16;
            float p0[16], p1[16];
            float tmax0 = -1e30f, tmax1 = -1e30f;

#pragma unroll
            for (int jj = 0; jj < 16; ++jj) {
                const int j = c16 + jj;
                const u64* kp = (const u64*)(Ks + j * HD + g * 32);
                u64 a0 = 0ull, a1 = 0ull;
#pragma unroll
                for (int i2 = 0; i2 < 16; ++i2) {
                    u64 kv = kp[i2];
                    a0 = ffma2(Qr0[i2], kv, a0);
                    a1 = ffma2(Qr1[i2], kv, a1);
                }
                float s0 = hadd2(a0);
                float s1 = hadd2(a1);
                s0 += __shfl_xor_sync(0xffffffffu, s0, 1);
                s0 += __shfl_xor_sync(0xffffffffu, s0, 2);
                s1 += __shfl_xor_sync(0xffffffffu, s1, 1);
                s1 += __shfl_xor_sync(0xffffffffu, s1, 2);
                if (diag) {
                    int jg = ktbase + j;
                    if (jg > q0) s0 = -1e30f;
                    if (jg > q1) s1 = -1e30f;
                }
                p0[jj] = s0; p1[jj] = s1;
                tmax0 = fmaxf(tmax0, s0);
                tmax1 = fmaxf(tmax1, s1);
            }

            float mn0 = fmaxf(rm0, tmax0);
            float mn1 = fmaxf(rm1, tmax1);
            float e0 = __expf(rm0 - mn0);
            float e1 = __expf(rm1 - mn1);
            rm0 = mn0; rm1 = mn1;
            float sum0 = 0.0f, sum1 = 0.0f;
#pragma unroll
            for (int jj = 0; jj < 16; ++jj) {
                p0[jj] = __expf(p0[jj] - mn0); sum0 += p0[jj];
                p1[jj] = __expf(p1[jj] - mn1); sum1 += p1[jj];
            }
            l0 = l0 * e0 + sum0;
            l1 = l1 * e1 + sum1;
            {
                u64 e0p = splat2(e0), e1p = splat2(e1);
#pragma unroll
                for (int i2 = 0; i2 < 16; ++i2) {
                    O0[i2] = fmul2(O0[i2], e0p);
                    O1[i2] = fmul2(O1[i2], e1p);
                }
            }

#pragma unroll
            for (int jj = 0; jj < 16; ++jj) {
                const int j = c16 + jj;
                const u64* vp = (const u64*)(Vs + j * HD + g * 32);
                u64 pp0 = splat2(p0[jj]);
                u64 pp1 = splat2(p1[jj]);
#pragma unroll
                for (int i2 = 0; i2 < 16; ++i2) {
                    u64 vv = vp[i2];
                    O0[i2] = ffma2(pp0, vv, O0[i2]);
                    O1[i2] = ffma2(pp1, vv, O1[i2]);
                }
            }
        }
    }

    u64 iv0 = splat2(1.0f / l0);
    u64 iv1 = splat2(1.0f / l1);
    u64* op0 = (u64*)(out + (size_t)q0 * (NH * HD) + h * HD + g * 32);
    u64* op1 = (u64*)(out + (size_t)q1 * (NH * HD) + h * HD + g * 32);
#pragma unroll
    for (int i2 = 0; i2 < 16; ++i2) {
        op0[i2] = fmul2(O0[i2], iv0);
        op1[i2] = fmul2(O1[i2], iv1);
    }
}

// ---------------- launch ----------------
extern "C" void kernel_launch(void* const* d_in, const int* in_sizes, int n_in,
                              void* d_out, int out_size) {
    const float* hs   = (const float*)d_in[0];   // [2048, 4096]
    const float* wqkv = (const float*)d_in[1];   // [6144, 4096]
    const float* wo   = (const float*)d_in[2];   // [4096, 4096]
    float* out = (float*)d_out;                  // [2048, 4096]

    cudaFuncSetAttribute(gemm3_hmma, cudaFuncAttributeMaxDynamicSharedMemorySize,
                         G_SMEM_BYTES);

    void *p_qkv, *p_attn, *p_hh, *p_hl, *p_qh, *p_ql, *p_oh, *p_ol, *p_ah, *p_al;
    cudaGetSymbolAddress(&p_qkv, g_qkv);
    cudaGetSymbolAddress(&p_attn, g_attn);
    cudaGetSymbolAddress(&p_hh, g_hs_hi);   cudaGetSymbolAddress(&p_hl, g_hs_lo);
    cudaGetSymbolAddress(&p_qh, g_wqkv_hi); cudaGetSymbolAddress(&p_ql, g_wqkv_lo);
    cudaGetSymbolAddress(&p_oh, g_wo_hi);   cudaGetSymbolAddress(&p_ol, g_wo_lo);
    cudaGetSymbolAddress(&p_ah, g_ao_hi);   cudaGetSymbolAddress(&p_al, g_ao_lo);

    // 1) split fp32 inputs into bf16 hi/lo pairs
    {
        int n1 = S_LEN * HID, n2 = QKV_OUT * HID, n3 = HID * HID;
        split_kernel<<<(n1 + 255) / 256, 256>>>(hs,   (__nv_bfloat16*)p_hh, (__nv_bfloat16*)p_hl, n1);
        split_kernel<<<(n2 + 255) / 256, 256>>>(wqkv, (__nv_bfloat16*)p_qh, (__nv_bfloat16*)p_ql, n2);
        split_kernel<<<(n3 + 255) / 256, 256>>>(wo,   (__nv_bfloat16*)p_oh, (__nv_bfloat16*)p_ol, n3);
    }
    // 2) QKV projection (3xBF16 HMMA): [2048,6144] = hs @ wqkv^T
    {
        dim3 grid(QKV_OUT / 128, S_LEN / 128);
        gemm3_hmma<<<grid, 256, G_SMEM_BYTES>>>(
            (const __nv_bfloat16*)p_hh, (const __nv_bfloat16*)p_hl,
            (const __nv_bfloat16*)p_qh, (const __nv_bfloat16*)p_ql,
            (float*)p_qkv, S_LEN, QKV_OUT, HID);
    }
    // 3) RoPE
    {
        int total = S_LEN * (NH + NKV) * 64;
        rope_kernel<<<(total + 255) / 256, 256>>>();
    }
    // 4) causal GQA flash attention -> g_attn
    {
        dim3 grid(S_LEN / 128, NH);
        attn_kernel<<<grid, 256>>>();
    }
    // 5) split attention output
    {
        int n4 = S_LEN * HID;
        split_kernel<<<(n4 + 255) / 256, 256>>>((const float*)p_attn,
                                                (__nv_bfloat16*)p_ah, (__nv_bfloat16*)p_al, n4);
    }
    // 6) output projection (3xBF16 HMMA): out = attn @ wo^T
    {
        dim3 grid(HID / 128, S_LEN / 128);
        gemm3_hmma<<<grid, 256, G_SMEM_BYTES>>>(
            (const __nv_bfloat16*)p_ah, (const __nv_bfloat16*)p_al,
            (const __nv_bfloat16*)p_oh, (const __nv_bfloat16*)p_ol,
            out, S_LEN, HID, HID);
    }
}